// round 16
// baseline (speedup 1.0000x reference)
#include <cuda_runtime.h>
#include <cuda_bf16.h>
#include <cstdint>
#include <cstring>

// Problem constants
#define BB 8
#define NN 128
#define CC 64
#define INV_AVG (1.0f/49.0f)
#define NEG_SLOPE 0.01f

// ---------------- scratch (device globals; no allocation) ----------------
// B fragments, hi/lo interleaved: uint4 per (kc8, tile, lane) = {bh0, bh1, bl0, bl1}
// u32 index base = ((kc8*8 + tile)*32 + lane)*4
__device__ __align__(16) uint32_t g_Bf[8192];
__device__ __align__(16) float g_Wmat[192*192];     // stats->U/V/Dg weights [k][o], o=(g<<6)|s
__device__ __align__(16) float g_stats[BB*NN*192];  // per token: [diag | rowsum/49 | colsum/49]
__device__ float g_W2[BB*2*CC];                     // per-batch: [W | Wd]
__device__ __align__(16) float g_U [BB*NN*CC];      // i-indexed adds (+W+bias)
__device__ __align__(16) float g_V [BB*NN*CC];      // j-indexed adds
__device__ __align__(16) float g_Dg[BB*NN*CC];      // diagonal adds (+Wd+diag_bias)

// ---------------- PTX helpers ----------------
__device__ __forceinline__ void cpa16(unsigned dst, const void* src) {
    asm volatile("cp.async.cg.shared.global [%0], [%1], 16;" :: "r"(dst), "l"(src));
}
__device__ __forceinline__ void cpa_commit() { asm volatile("cp.async.commit_group;"); }
template <int N> __device__ __forceinline__ void cpa_wait() {
    asm volatile("cp.async.wait_group %0;" :: "n"(N));
}

__device__ __forceinline__ void ldm_x4(uint32_t* r, uint32_t addr) {
    asm volatile("ldmatrix.sync.aligned.m8n8.x4.shared.b16 {%0,%1,%2,%3}, [%4];"
                 : "=r"(r[0]), "=r"(r[1]), "=r"(r[2]), "=r"(r[3]) : "r"(addr));
}

__device__ __forceinline__ void mma_bf16(float* c, const uint32_t* a, uint32_t b0, uint32_t b1) {
    asm volatile("mma.sync.aligned.m16n8k16.row.col.f32.bf16.bf16.f32 "
                 "{%0,%1,%2,%3}, {%4,%5,%6,%7}, {%8,%9}, {%0,%1,%2,%3};"
                 : "+f"(c[0]), "+f"(c[1]), "+f"(c[2]), "+f"(c[3])
                 : "r"(a[0]), "r"(a[1]), "r"(a[2]), "r"(a[3]), "r"(b0), "r"(b1));
}

__device__ __forceinline__ uint32_t pk2(__nv_bfloat16 x, __nv_bfloat16 y) {
    __nv_bfloat162 h; h.x = x; h.y = y;
    uint32_t r; memcpy(&r, &h, 4); return r;
}

// ---------------- P1: per-token stats, float4 vectorized (+ side jobs) ----------------
__global__ __launch_bounds__(256) void stats_kernel(const float* __restrict__ in,
                             const float* __restrict__ c00, const float* __restrict__ c01,
                             const float* __restrict__ c10, const float* __restrict__ c11) {
    int bt = blockIdx.x;            // 0..1023
    int b = bt >> 7, t = bt & 127;
    int tid = threadIdx.x;          // 256
    int dq = tid & 15;              // d-quad (0..15) -> d = dq*4..+3
    int jl = tid >> 4;              // j-lane (0..15)

    // side job A: blocks 0..31 compute main-GEMM B, hi/lo-interleaved fragment order
    if (bt < 32) {
        int idx = bt * 256 + tid;   // 8192 = 128*64
        int s = idx & 63;
        int k = idx >> 6;
        int dd = k & 63;
        int bop = (k < 64) ? 3 : 4; // op3 = identity, op4 = transpose
        float v = c00[dd*15 + bop] * c10[dd*64 + s] + c01[s*15 + bop] * c11[dd*64 + s];
        __nv_bfloat16 hi = __float2bfloat16(v);
        __nv_bfloat16 lo = __float2bfloat16(v - __bfloat162float(hi));
        int kc8 = k >> 4, kr = k & 15;
        int reg = kr >> 3, tg = (kr & 7) >> 1, e = kr & 1;
        int tile = s >> 3, g = s & 7;
        int lane = g*4 + tg;
        int base = ((kc8*8 + tile)*32 + lane)*4;
        ((__nv_bfloat16*)g_Bf)[(base + reg)*2 + e]     = hi;
        ((__nv_bfloat16*)g_Bf)[(base + 2 + reg)*2 + e] = lo;
    }
    // side job B: blocks 32..175 build g_Wmat (one element each)
    else if (bt < 176) {
        int w = (bt - 32) * 256 + tid;      // 0..36863
        int o = w % 192;
        int k = w / 192;
        int g = o >> 6, s = o & 63;
        int kind = k >> 6, dd = k & 63;
        const int opmap[3][3] = { {1, 9, 11},    // U : diag, rowsum, colsum
                                  {2, 10, 12},   // V
                                  {0, 5, 6} };   // Dg
        int op = opmap[g][kind];
        g_Wmat[w] = c00[dd*15 + op] * c10[dd*64 + s] + c01[s*15 + op] * c11[dd*64 + s];
    }

    const float* rowbase = in + (size_t)((b*NN + t) * NN) * CC;   // in[b,t,j,:]
    const float* colbase = in + ((size_t)b*NN*NN + t) * CC;       // in[b,i,t,:]

    float4 rs = make_float4(0.f, 0.f, 0.f, 0.f);
#pragma unroll 8
    for (int j = jl; j < NN; j += 16) {
        float4 v = *(const float4*)(rowbase + j*CC + dq*4);
        rs.x += v.x; rs.y += v.y; rs.z += v.z; rs.w += v.w;
    }
    float4 cs = make_float4(0.f, 0.f, 0.f, 0.f);
#pragma unroll 8
    for (int i = jl; i < NN; i += 16) {
        float4 v = *(const float4*)(colbase + (size_t)i*NN*CC + dq*4);
        cs.x += v.x; cs.y += v.y; cs.z += v.z; cs.w += v.w;
    }

    __shared__ float red[2][16][64];
    *(float4*)&red[0][jl][dq*4] = rs;
    *(float4*)&red[1][jl][dq*4] = cs;
    __syncthreads();

    if (tid < 128) {
        int which = tid >> 6;     // 0 = rowsum(+diag), 1 = colsum
        int d = tid & 63;
        float s = 0.f;
#pragma unroll
        for (int p = 0; p < 16; p++) s += red[which][p][d];
        int o = (b*NN + t)*192;
        if (which == 0) {
            g_stats[o + 64 + d] = s * INV_AVG;           // rowsum
            g_stats[o + d]      = rowbase[t*CC + d];     // diag
        } else {
            g_stats[o + 128 + d] = s * INV_AVG;          // colsum
        }
    }
}

// ---------------- P1b: fused trace/allsum reduction + per-batch W/Wd ----------------
__global__ __launch_bounds__(256) void tw_kernel(const float* __restrict__ c00,
                                                 const float* __restrict__ c01,
                                                 const float* __restrict__ c10,
                                                 const float* __restrict__ c11) {
    int b = blockIdx.x;     // 8
    int tid = threadIdx.x;
    int d = tid & 63, part = tid >> 6;   // 4 partials per d

    float tr = 0.f, as = 0.f;
    const float* sb = g_stats + (size_t)(b*NN)*192;
#pragma unroll 8
    for (int t = part; t < NN; t += 4) {
        tr += sb[t*192 + d];
        as += sb[t*192 + 64 + d];
    }
    __shared__ float red[2][4][64];
    __shared__ float strace[64], sasum[64];
    red[0][part][d] = tr;
    red[1][part][d] = as;
    __syncthreads();
    if (part == 0) {
        strace[d] = (red[0][0][d] + red[0][1][d] + red[0][2][d] + red[0][3][d]) * INV_AVG;
        sasum [d] = (red[1][0][d] + red[1][1][d] + red[1][2][d] + red[1][3][d]) * INV_AVG;
    }
    __syncthreads();

    if (tid < 64) {
        int s = tid;
        float c13b = c01[s*15 + 13], c14b = c01[s*15 + 14];
        float c7b  = c01[s*15 + 7],  c8b  = c01[s*15 + 8];
        float W = 0.f, Wd = 0.f;
#pragma unroll 4
        for (int dd = 0; dd < 64; dd++) {
            float f10 = c10[dd*64 + s], f11 = c11[dd*64 + s];
            float t0 = strace[dd], a0 = sasum[dd];
            W  += t0*(c00[dd*15 + 13]*f10 + c13b*f11) + a0*(c00[dd*15 + 14]*f10 + c14b*f11);
            Wd += t0*(c00[dd*15 + 7 ]*f10 + c7b *f11) + a0*(c00[dd*15 + 8 ]*f10 + c8b *f11);
        }
        g_W2[(b*2 + 0)*CC + s] = W;
        g_W2[(b*2 + 1)*CC + s] = Wd;
    }
}

// ---------------- P2: stats GEMM -> U/V/Dg  (pure GEMM; Wmat precomputed) ----------------
__global__ __launch_bounds__(256) void cgemm_kernel(const float* __restrict__ bias,
                                                    const float* __restrict__ dbias) {
    int tok0 = blockIdx.x * 16;
    int g    = blockIdx.y;
    int tid  = threadIdx.x;
    int ty   = tid >> 4;        // token 0..15
    int sq   = tid & 15;        // s-quad

    __shared__ float sS[16][196];   // stats [tok][k]
    __shared__ float sW[192][64];   // weight slice [k][s]

    uint32_t sSb = (uint32_t)__cvta_generic_to_shared(&sS[0][0]);
    uint32_t sWb = (uint32_t)__cvta_generic_to_shared(&sW[0][0]);

#pragma unroll
    for (int q = 0; q < 3; q++) {
        int e = tid + q*256;
        int tk = e / 48;
        int kq = e % 48;
        cpa16(sSb + (uint32_t)((tk*196 + kq*4) * 4),
              &g_stats[(tok0 + tk)*192 + kq*4]);
    }
#pragma unroll
    for (int q = 0; q < 12; q++) {
        int e = tid + q*256;
        int k = e >> 4;
        int c4 = (e & 15) * 4;
        cpa16(sWb + (uint32_t)((k*64 + c4) * 4),
              &g_Wmat[k*192 + g*64 + c4]);
    }
    cpa_commit();
    cpa_wait<0>();
    __syncthreads();

    float acc[4] = {0.f, 0.f, 0.f, 0.f};
#pragma unroll 8
    for (int k = 0; k < 192; k++) {
        float a = sS[ty][k];
        float4 w = *(const float4*)&sW[k][sq*4];
        acc[0] += a * w.x;
        acc[1] += a * w.y;
        acc[2] += a * w.z;
        acc[3] += a * w.w;
    }

    int tok = tok0 + ty;
    int b = tok >> 7;
    int s0 = sq * 4;
    int oi = tok*CC + s0;
#pragma unroll
    for (int c = 0; c < 4; c++) {
        int s = s0 + c;
        float v = acc[c];
        if (g == 0)      g_U[oi + c]  = v + g_W2[(b*2 + 0)*CC + s] + bias[s];
        else if (g == 1) g_V[oi + c]  = v;
        else             g_Dg[oi + c] = v + g_W2[(b*2 + 1)*CC + s] + dbias[s];
    }
}

// ---------------- P3: main GEMM on mma.sync (bf16 hi/lo, M=64 tiles, occ 4) ----------------
// Grid = 2048 CTAs (b, i, jhalf). Per CTA: D[j,s] for j in [j0, j0+64), s 0..63, K=128.
// 8 warps: 2(m) x 4(n), each 32m x 16n via 2x2 m16n8k16 tiles, 3 products each.
// A bf16 hi/lo in swizzled smem; B frags hi/lo in one uint4 LDG.128 (L1-broadcast hot).
#define ACC_STRIDE 68
#define DSM_BYTES 32768

__global__ __launch_bounds__(256, 4) void main_mma_kernel(const float* __restrict__ in,
                                                          const float* __restrict__ mask,
                                                          float* __restrict__ out) {
    extern __shared__ __align__(128) char dsm[];
    __shared__ float sU[64], sDg[64];

    int tid = threadIdx.x;
    int lane = tid & 31;
    int w = tid >> 5;
    int wm = w >> 2;          // 0..1  -> m base = wm*32
    int wn = w & 3;           // 0..3  -> n base = wn*16
    int bx = blockIdx.x;
    int b  = bx >> 8;
    int i  = (bx & 255) >> 1;
    int j0 = (bx & 1) * 64;

    uint32_t sbase = (uint32_t)__cvta_generic_to_shared(dsm);
    float* sAcc = (float*)dsm;

    if (tid < 64) {
        sU[tid]  = g_U [(b*NN + i)*CC + tid];
        sDg[tid] = g_Dg[(b*NN + i)*CC + tid];
    }

    // ldmatrix lane geometry (A)
    int a_row = ((lane >> 3) & 1)*8 + (lane & 7);
    int a_csel = (lane >> 4) & 1;               // chunk select within k16

    const float* Ab = in + (size_t)b * NN * NN * CC;
    int cr = tid >> 2;                 // conversion row (0..63)
    int cq = tid & 3;                  // 16-float segment within the 64-col row

    // ---- convert both A k-halves: fp32 -> bf16 hi/lo, swizzled 8B STS ----
#pragma unroll
    for (int khalf = 0; khalf < 2; khalf++) {
        const float* srcrow = (khalf == 0) ? (Ab + ((size_t)i*NN + (j0 + cr))*CC)
                                           : (Ab + ((size_t)(j0 + cr)*NN + i)*CC);
        uint32_t hibase = sbase + (uint32_t)(khalf*8192);     // hi: [0,8K)+[8K,16K)
        uint32_t lobase = hibase + 16384;                      // lo: [16K,24K)+[24K,32K)
#pragma unroll
        for (int c = 0; c < 4; c++) {
            int col = cq*16 + c*4;
            float4 v = *(const float4*)(srcrow + col);
            __nv_bfloat16 h0 = __float2bfloat16(v.x), h1 = __float2bfloat16(v.y);
            __nv_bfloat16 h2 = __float2bfloat16(v.z), h3 = __float2bfloat16(v.w);
            uint32_t H0 = pk2(h0, h1), H1 = pk2(h2, h3);
            uint32_t L0 = pk2(__float2bfloat16(v.x - __bfloat162float(h0)),
                              __float2bfloat16(v.y - __bfloat162float(h1)));
            uint32_t L1 = pk2(__float2bfloat16(v.z - __bfloat162float(h2)),
                              __float2bfloat16(v.w - __bfloat162float(h3)));
            int chunk = cq*2 + (c >> 1);                 // 16B chunk within the khalf row-half
            int sub = (c & 1) * 8;                       // 8B sub-offset within chunk
            uint32_t off = (uint32_t)(cr*128 + (((chunk ^ (cr & 7)) << 4) | sub));
            asm volatile("st.shared.v2.b32 [%0], {%1, %2};"
                         :: "r"(hibase + off), "r"(H0), "r"(H1));
            asm volatile("st.shared.v2.b32 [%0], {%1, %2};"
                         :: "r"(lobase + off), "r"(L0), "r"(L1));
        }
    }
    __syncthreads();

    float acc[2][2][4];
#pragma unroll
    for (int mt = 0; mt < 2; mt++)
#pragma unroll
        for (int nt = 0; nt < 2; nt++)
#pragma unroll
            for (int e = 0; e < 4; e++) acc[mt][nt][e] = 0.f;

    // ---- single mma loop over 8 k16 chunks ----
#pragma unroll
    for (int kc8 = 0; kc8 < 8; kc8++) {
        int khalf = kc8 >> 2, kc = kc8 & 3;
        uint32_t hibase = sbase + (uint32_t)(khalf*8192);
        uint32_t lobase = hibase + 16384;
        uint32_t ah[2][4], al[2][4];
#pragma unroll
        for (int mt = 0; mt < 2; mt++) {
            int row = wm*32 + mt*16 + a_row;
            int chunk = kc*2 + a_csel;
            uint32_t off = (uint32_t)(row*128 + ((chunk ^ (row & 7)) << 4));
            ldm_x4(ah[mt], hibase + off);
            ldm_x4(al[mt], lobase + off);
        }
        uint4 bv[2];
#pragma unroll
        for (int nt = 0; nt < 2; nt++) {
            int idx = ((kc8*8 + wn*2 + nt)*32 + lane)*4;
            bv[nt] = *(const uint4*)&g_Bf[idx];
        }
#pragma unroll
        for (int mt = 0; mt < 2; mt++)
#pragma unroll
            for (int nt = 0; nt < 2; nt++) {
                mma_bf16(acc[mt][nt], ah[mt], bv[nt].x, bv[nt].y);
                mma_bf16(acc[mt][nt], ah[mt], bv[nt].z, bv[nt].w);
                mma_bf16(acc[mt][nt], al[mt], bv[nt].x, bv[nt].y);
            }
    }
    __syncthreads();

    // ---- restage acc through smem (aliases A tables) ----
    {
        int g4 = lane >> 2, q = lane & 3;
#pragma unroll
        for (int mt = 0; mt < 2; mt++)
#pragma unroll
            for (int half = 0; half < 2; half++) {
                int j = wm*32 + mt*16 + g4 + half*8;
#pragma unroll
                for (int nt = 0; nt < 2; nt++) {
                    int s = wn*16 + nt*8 + q*2;
                    *(float2*)&sAcc[j*ACC_STRIDE + s] =
                        make_float2(acc[mt][nt][half*2], acc[mt][nt][half*2+1]);
                }
            }
    }
    __syncthreads();

    // ---- coalesced epilogue: + U + V + diag*Dg; leaky-relu; * mask ----
    {
        int rsel = lane >> 3;          // 0..3
        int csel = lane & 7;           // 0..7
        const float* mrow = mask + (size_t)(b*NN + i)*NN + j0;
        float* obase = out + ((size_t)(b*NN + i)*NN + j0)*CC;
#pragma unroll
        for (int r4 = 0; r4 < 2; r4++) {
            int row = w*8 + r4*4 + rsel;          // 0..63
            float mk = mrow[row];
            bool od = (j0 + row == i);
            const float* vrow = g_V + (b*NN + j0 + row)*CC;
#pragma unroll
            for (int h = 0; h < 2; h++) {
                int col = h*32 + csel*4;
                float4 a4 = *(const float4*)&sAcc[row*ACC_STRIDE + col];
                float4 vv = *(const float4*)&vrow[col];
                float4 u4 = *(const float4*)&sU[col];
                float o0 = a4.x + u4.x + vv.x;
                float o1 = a4.y + u4.y + vv.y;
                float o2 = a4.z + u4.z + vv.z;
                float o3 = a4.w + u4.w + vv.w;
                if (od) {
                    float4 d4 = *(const float4*)&sDg[col];
                    o0 += d4.x; o1 += d4.y; o2 += d4.z; o3 += d4.w;
                }
                o0 = (o0 > 0.f) ? o0 : NEG_SLOPE * o0;
                o1 = (o1 > 0.f) ? o1 : NEG_SLOPE * o1;
                o2 = (o2 > 0.f) ? o2 : NEG_SLOPE * o2;
                o3 = (o3 > 0.f) ? o3 : NEG_SLOPE * o3;
                *(float4*)&obase[(size_t)row*CC + col] =
                    make_float4(o0*mk, o1*mk, o2*mk, o3*mk);
            }
        }
    }
}

// ---------------- launch ----------------
extern "C" void kernel_launch(void* const* d_in, const int* in_sizes, int n_in,
                              void* d_out, int out_size) {
    const float* in     = (const float*)d_in[0];
    const float* mask   = (const float*)d_in[1];
    // d_in[2] = nobj (unused: reference hard-codes average_nobj = 49)
    const float* c00    = (const float*)d_in[3];
    const float* c01    = (const float*)d_in[4];
    const float* c10    = (const float*)d_in[5];
    const float* c11    = (const float*)d_in[6];
    const float* bias   = (const float*)d_in[7];
    const float* dbias  = (const float*)d_in[8];
    float* out = (float*)d_out;

    stats_kernel<<<BB*NN, 256>>>(in, c00, c01, c10, c11);
    tw_kernel<<<BB, 256>>>(c00, c01, c10, c11);
    cgemm_kernel<<<dim3(64, 3), 256>>>(bias, dbias);
    main_mma_kernel<<<BB*NN*2, 256, DSM_BYTES>>>(in, mask, out);
}

// round 17
// speedup vs baseline: 1.4903x; 1.4903x over previous
#include <cuda_runtime.h>
#include <cuda_bf16.h>
#include <cstdint>
#include <cstring>

// Problem constants
#define BB 8
#define NN 128
#define CC 64
#define INV_AVG (1.0f/49.0f)
#define NEG_SLOPE 0.01f

// ---------------- scratch (device globals; no allocation) ----------------
// B fragments, hi/lo interleaved: uint4 per (kc8, tile, lane) = {bh0, bh1, bl0, bl1}
// u32 index base = ((kc8*8 + tile)*32 + lane)*4
__device__ __align__(16) uint32_t g_Bf[8192];
__device__ __align__(16) float g_Wmat[192*192];     // stats->U/V/Dg weights [k][o], o=(g<<6)|s
__device__ __align__(16) float g_stats[BB*NN*192];  // per token: [diag | rowsum/49 | colsum/49]
__device__ float g_W2[BB*2*CC];                     // per-batch: [W | Wd]
__device__ __align__(16) float g_U [BB*NN*CC];      // i-indexed adds (+W+bias)
__device__ __align__(16) float g_V [BB*NN*CC];      // j-indexed adds
__device__ __align__(16) float g_Dg[BB*NN*CC];      // diagonal adds (+Wd+diag_bias)

// ---------------- PTX helpers ----------------
__device__ __forceinline__ void cpa16(unsigned dst, const void* src) {
    asm volatile("cp.async.cg.shared.global [%0], [%1], 16;" :: "r"(dst), "l"(src));
}
__device__ __forceinline__ void cpa_commit() { asm volatile("cp.async.commit_group;"); }
template <int N> __device__ __forceinline__ void cpa_wait() {
    asm volatile("cp.async.wait_group %0;" :: "n"(N));
}

__device__ __forceinline__ void ldm_x4(uint32_t* r, uint32_t addr) {
    asm volatile("ldmatrix.sync.aligned.m8n8.x4.shared.b16 {%0,%1,%2,%3}, [%4];"
                 : "=r"(r[0]), "=r"(r[1]), "=r"(r[2]), "=r"(r[3]) : "r"(addr));
}

__device__ __forceinline__ void mma_bf16(float* c, const uint32_t* a, uint32_t b0, uint32_t b1) {
    asm volatile("mma.sync.aligned.m16n8k16.row.col.f32.bf16.bf16.f32 "
                 "{%0,%1,%2,%3}, {%4,%5,%6,%7}, {%8,%9}, {%0,%1,%2,%3};"
                 : "+f"(c[0]), "+f"(c[1]), "+f"(c[2]), "+f"(c[3])
                 : "r"(a[0]), "r"(a[1]), "r"(a[2]), "r"(a[3]), "r"(b0), "r"(b1));
}

__device__ __forceinline__ uint32_t pk2(__nv_bfloat16 x, __nv_bfloat16 y) {
    __nv_bfloat162 h; h.x = x; h.y = y;
    uint32_t r; memcpy(&r, &h, 4); return r;
}

// ---------------- P1: per-token stats (+ side jobs: B frags, Wmat) ----------------
__global__ void stats_kernel(const float* __restrict__ in,
                             const float* __restrict__ c00, const float* __restrict__ c01,
                             const float* __restrict__ c10, const float* __restrict__ c11) {
    int bt = blockIdx.x;            // 0..1023
    int b = bt >> 7, t = bt & 127;
    int tid = threadIdx.x;          // 256
    int d  = tid & 63;
    int jl = tid >> 6;              // 0..3

    // side job A: blocks 0..31 compute main-GEMM B, hi/lo-interleaved fragment order
    if (bt < 32) {
        int idx = bt * 256 + tid;   // 8192 = 128*64
        int s = idx & 63;
        int k = idx >> 6;
        int dd = k & 63;
        int bop = (k < 64) ? 3 : 4; // op3 = identity, op4 = transpose
        float v = c00[dd*15 + bop] * c10[dd*64 + s] + c01[s*15 + bop] * c11[dd*64 + s];
        __nv_bfloat16 hi = __float2bfloat16(v);
        __nv_bfloat16 lo = __float2bfloat16(v - __bfloat162float(hi));
        int kc8 = k >> 4, kr = k & 15;
        int reg = kr >> 3, tg = (kr & 7) >> 1, e = kr & 1;
        int tile = s >> 3, g = s & 7;
        int lane = g*4 + tg;
        int base = ((kc8*8 + tile)*32 + lane)*4;
        ((__nv_bfloat16*)g_Bf)[(base + reg)*2 + e]     = hi;
        ((__nv_bfloat16*)g_Bf)[(base + 2 + reg)*2 + e] = lo;
    }
    // side job B: blocks 32..175 build g_Wmat (one element each)
    else if (bt < 176) {
        int w = (bt - 32) * 256 + tid;      // 0..36863
        int o = w % 192;
        int k = w / 192;
        int g = o >> 6, s = o & 63;
        int kind = k >> 6, dd = k & 63;
        const int opmap[3][3] = { {1, 9, 11},    // U : diag, rowsum, colsum
                                  {2, 10, 12},   // V
                                  {0, 5, 6} };   // Dg
        int op = opmap[g][kind];
        g_Wmat[w] = c00[dd*15 + op] * c10[dd*64 + s] + c01[s*15 + op] * c11[dd*64 + s];
    }

    const float* rowbase = in + (size_t)((b*NN + t) * NN) * CC;   // in[b,t,j,d]
    float rs = 0.f;
#pragma unroll 8
    for (int j = jl; j < NN; j += 4) rs += rowbase[j*CC + d];

    const float* colbase = in + ((size_t)b*NN*NN + t) * CC;       // in[b,i,t,d]
    float cs = 0.f;
#pragma unroll 8
    for (int i = jl; i < NN; i += 4) cs += colbase[(size_t)i*NN*CC + d];

    __shared__ float red[2][4][64];
    red[0][jl][d] = rs;
    red[1][jl][d] = cs;
    __syncthreads();
    if (jl == 0) {
        float r = red[0][0][d] + red[0][1][d] + red[0][2][d] + red[0][3][d];
        float c = red[1][0][d] + red[1][1][d] + red[1][2][d] + red[1][3][d];
        int o = (b*NN + t)*192;
        g_stats[o + d]       = rowbase[t*CC + d];   // diag
        g_stats[o + 64 + d]  = r * INV_AVG;         // rowsum
        g_stats[o + 128 + d] = c * INV_AVG;         // colsum
    }
}

// ---------------- P1b: fused trace/allsum reduction + per-batch W/Wd ----------------
__global__ __launch_bounds__(256) void tw_kernel(const float* __restrict__ c00,
                                                 const float* __restrict__ c01,
                                                 const float* __restrict__ c10,
                                                 const float* __restrict__ c11) {
    int b = blockIdx.x;     // 8
    int tid = threadIdx.x;
    int d = tid & 63, part = tid >> 6;   // 4 partials per d

    float tr = 0.f, as = 0.f;
    const float* sb = g_stats + (size_t)(b*NN)*192;
#pragma unroll 8
    for (int t = part; t < NN; t += 4) {
        tr += sb[t*192 + d];
        as += sb[t*192 + 64 + d];
    }
    __shared__ float red[2][4][64];
    __shared__ float strace[64], sasum[64];
    red[0][part][d] = tr;
    red[1][part][d] = as;
    __syncthreads();
    if (part == 0) {
        strace[d] = (red[0][0][d] + red[0][1][d] + red[0][2][d] + red[0][3][d]) * INV_AVG;
        sasum [d] = (red[1][0][d] + red[1][1][d] + red[1][2][d] + red[1][3][d]) * INV_AVG;
    }
    __syncthreads();

    if (tid < 64) {
        int s = tid;
        float c13b = c01[s*15 + 13], c14b = c01[s*15 + 14];
        float c7b  = c01[s*15 + 7],  c8b  = c01[s*15 + 8];
        float W = 0.f, Wd = 0.f;
#pragma unroll 4
        for (int dd = 0; dd < 64; dd++) {
            float f10 = c10[dd*64 + s], f11 = c11[dd*64 + s];
            float t0 = strace[dd], a0 = sasum[dd];
            W  += t0*(c00[dd*15 + 13]*f10 + c13b*f11) + a0*(c00[dd*15 + 14]*f10 + c14b*f11);
            Wd += t0*(c00[dd*15 + 7 ]*f10 + c7b *f11) + a0*(c00[dd*15 + 8 ]*f10 + c8b *f11);
        }
        g_W2[(b*2 + 0)*CC + s] = W;
        g_W2[(b*2 + 1)*CC + s] = Wd;
    }
}

// ---------------- P2: stats GEMM -> U/V/Dg  (pure GEMM; Wmat precomputed) ----------------
__global__ __launch_bounds__(256) void cgemm_kernel(const float* __restrict__ bias,
                                                    const float* __restrict__ dbias) {
    int tok0 = blockIdx.x * 16;
    int g    = blockIdx.y;
    int tid  = threadIdx.x;
    int ty   = tid >> 4;        // token 0..15
    int sq   = tid & 15;        // s-quad

    __shared__ float sS[16][196];   // stats [tok][k]
    __shared__ float sW[192][64];   // weight slice [k][s]

    uint32_t sSb = (uint32_t)__cvta_generic_to_shared(&sS[0][0]);
    uint32_t sWb = (uint32_t)__cvta_generic_to_shared(&sW[0][0]);

#pragma unroll
    for (int q = 0; q < 3; q++) {
        int e = tid + q*256;
        int tk = e / 48;
        int kq = e % 48;
        cpa16(sSb + (uint32_t)((tk*196 + kq*4) * 4),
              &g_stats[(tok0 + tk)*192 + kq*4]);
    }
#pragma unroll
    for (int q = 0; q < 12; q++) {
        int e = tid + q*256;
        int k = e >> 4;
        int c4 = (e & 15) * 4;
        cpa16(sWb + (uint32_t)((k*64 + c4) * 4),
              &g_Wmat[k*192 + g*64 + c4]);
    }
    cpa_commit();
    cpa_wait<0>();
    __syncthreads();

    float acc[4] = {0.f, 0.f, 0.f, 0.f};
#pragma unroll 8
    for (int k = 0; k < 192; k++) {
        float a = sS[ty][k];
        float4 w = *(const float4*)&sW[k][sq*4];
        acc[0] += a * w.x;
        acc[1] += a * w.y;
        acc[2] += a * w.z;
        acc[3] += a * w.w;
    }

    int tok = tok0 + ty;
    int b = tok >> 7;
    int s0 = sq * 4;
    int oi = tok*CC + s0;
#pragma unroll
    for (int c = 0; c < 4; c++) {
        int s = s0 + c;
        float v = acc[c];
        if (g == 0)      g_U[oi + c]  = v + g_W2[(b*2 + 0)*CC + s] + bias[s];
        else if (g == 1) g_V[oi + c]  = v;
        else             g_Dg[oi + c] = v + g_W2[(b*2 + 1)*CC + s] + dbias[s];
    }
}

// ---------------- P3: main GEMM on mma.sync (bf16 hi/lo, M=64 tiles) ----------------
// Grid = 2048 CTAs (b, i, jhalf). Per CTA: D[j,s] for j in [j0, j0+64), s 0..63, K=128.
// 8 warps: 2(m) x 4(n), each 32m x 16n via 2x2 m16n8k16 tiles, 3 products each.
// A bf16 hi/lo in swizzled smem; B frags hi/lo in one uint4 LDG.128 (L1-broadcast hot).
#define ACC_STRIDE 68
#define DSM_BYTES 32768

__global__ __launch_bounds__(256, 3) void main_mma_kernel(const float* __restrict__ in,
                                                          const float* __restrict__ mask,
                                                          float* __restrict__ out) {
    extern __shared__ __align__(128) char dsm[];
    __shared__ float sU[64], sDg[64];

    int tid = threadIdx.x;
    int lane = tid & 31;
    int w = tid >> 5;
    int wm = w >> 2;          // 0..1  -> m base = wm*32
    int wn = w & 3;           // 0..3  -> n base = wn*16
    int bx = blockIdx.x;
    int b  = bx >> 8;
    int i  = (bx & 255) >> 1;
    int j0 = (bx & 1) * 64;

    uint32_t sbase = (uint32_t)__cvta_generic_to_shared(dsm);
    float* sAcc = (float*)dsm;

    if (tid < 64) {
        sU[tid]  = g_U [(b*NN + i)*CC + tid];
        sDg[tid] = g_Dg[(b*NN + i)*CC + tid];
    }

    // ldmatrix lane geometry (A)
    int a_row = ((lane >> 3) & 1)*8 + (lane & 7);
    int a_csel = (lane >> 4) & 1;               // chunk select within k16

    const float* Ab = in + (size_t)b * NN * NN * CC;
    int cr = tid >> 2;                 // conversion row (0..63)
    int cq = tid & 3;                  // 16-float segment within the 64-col row

    // ---- convert both A k-halves: fp32 -> bf16 hi/lo, swizzled 8B STS ----
#pragma unroll
    for (int khalf = 0; khalf < 2; khalf++) {
        const float* srcrow = (khalf == 0) ? (Ab + ((size_t)i*NN + (j0 + cr))*CC)
                                           : (Ab + ((size_t)(j0 + cr)*NN + i)*CC);
        uint32_t hibase = sbase + (uint32_t)(khalf*8192);     // hi: [0,8K)+[8K,16K)
        uint32_t lobase = hibase + 16384;                      // lo: [16K,24K)+[24K,32K)
#pragma unroll
        for (int c = 0; c < 4; c++) {
            int col = cq*16 + c*4;
            float4 v = *(const float4*)(srcrow + col);
            __nv_bfloat16 h0 = __float2bfloat16(v.x), h1 = __float2bfloat16(v.y);
            __nv_bfloat16 h2 = __float2bfloat16(v.z), h3 = __float2bfloat16(v.w);
            uint32_t H0 = pk2(h0, h1), H1 = pk2(h2, h3);
            uint32_t L0 = pk2(__float2bfloat16(v.x - __bfloat162float(h0)),
                              __float2bfloat16(v.y - __bfloat162float(h1)));
            uint32_t L1 = pk2(__float2bfloat16(v.z - __bfloat162float(h2)),
                              __float2bfloat16(v.w - __bfloat162float(h3)));
            int chunk = cq*2 + (c >> 1);                 // 16B chunk within the khalf row-half
            int sub = (c & 1) * 8;                       // 8B sub-offset within chunk
            uint32_t off = (uint32_t)(cr*128 + (((chunk ^ (cr & 7)) << 4) | sub));
            asm volatile("st.shared.v2.b32 [%0], {%1, %2};"
                         :: "r"(hibase + off), "r"(H0), "r"(H1));
            asm volatile("st.shared.v2.b32 [%0], {%1, %2};"
                         :: "r"(lobase + off), "r"(L0), "r"(L1));
        }
    }
    __syncthreads();

    float acc[2][2][4];
#pragma unroll
    for (int mt = 0; mt < 2; mt++)
#pragma unroll
        for (int nt = 0; nt < 2; nt++)
#pragma unroll
            for (int e = 0; e < 4; e++) acc[mt][nt][e] = 0.f;

    // ---- single mma loop over 8 k16 chunks ----
    // smem layout per table: rows 0..63 x 128B, khalf selects 8KB block; chunk 0..7 within row
#pragma unroll
    for (int kc8 = 0; kc8 < 8; kc8++) {
        int khalf = kc8 >> 2, kc = kc8 & 3;
        uint32_t hibase = sbase + (uint32_t)(khalf*8192);
        uint32_t lobase = hibase + 16384;
        uint32_t ah[2][4], al[2][4];
#pragma unroll
        for (int mt = 0; mt < 2; mt++) {
            int row = wm*32 + mt*16 + a_row;
            int chunk = kc*2 + a_csel;
            uint32_t off = (uint32_t)(row*128 + ((chunk ^ (row & 7)) << 4));
            ldm_x4(ah[mt], hibase + off);
            ldm_x4(al[mt], lobase + off);
        }
        uint4 bv[2];
#pragma unroll
        for (int nt = 0; nt < 2; nt++) {
            int idx = ((kc8*8 + wn*2 + nt)*32 + lane)*4;
            bv[nt] = *(const uint4*)&g_Bf[idx];
        }
#pragma unroll
        for (int mt = 0; mt < 2; mt++)
#pragma unroll
            for (int nt = 0; nt < 2; nt++) {
                mma_bf16(acc[mt][nt], ah[mt], bv[nt].x, bv[nt].y);
                mma_bf16(acc[mt][nt], ah[mt], bv[nt].z, bv[nt].w);
                mma_bf16(acc[mt][nt], al[mt], bv[nt].x, bv[nt].y);
            }
    }
    __syncthreads();

    // ---- restage acc through smem (aliases A tables) ----
    {
        int g4 = lane >> 2, q = lane & 3;
#pragma unroll
        for (int mt = 0; mt < 2; mt++)
#pragma unroll
            for (int half = 0; half < 2; half++) {
                int j = wm*32 + mt*16 + g4 + half*8;
#pragma unroll
                for (int nt = 0; nt < 2; nt++) {
                    int s = wn*16 + nt*8 + q*2;
                    *(float2*)&sAcc[j*ACC_STRIDE + s] =
                        make_float2(acc[mt][nt][half*2], acc[mt][nt][half*2+1]);
                }
            }
    }
    __syncthreads();

    // ---- coalesced epilogue: + U + V + diag*Dg; leaky-relu; * mask ----
    {
        int rsel = lane >> 3;          // 0..3
        int csel = lane & 7;           // 0..7
        const float* mrow = mask + (size_t)(b*NN + i)*NN + j0;
        float* obase = out + ((size_t)(b*NN + i)*NN + j0)*CC;
#pragma unroll
        for (int r4 = 0; r4 < 2; r4++) {
            int row = w*8 + r4*4 + rsel;          // 0..63
            float mk = mrow[row];
            bool od = (j0 + row == i);
            const float* vrow = g_V + (b*NN + j0 + row)*CC;
#pragma unroll
            for (int h = 0; h < 2; h++) {
                int col = h*32 + csel*4;
                float4 a4 = *(const float4*)&sAcc[row*ACC_STRIDE + col];
                float4 vv = *(const float4*)&vrow[col];
                float4 u4 = *(const float4*)&sU[col];
                float o0 = a4.x + u4.x + vv.x;
                float o1 = a4.y + u4.y + vv.y;
                float o2 = a4.z + u4.z + vv.z;
                float o3 = a4.w + u4.w + vv.w;
                if (od) {
                    float4 d4 = *(const float4*)&sDg[col];
                    o0 += d4.x; o1 += d4.y; o2 += d4.z; o3 += d4.w;
                }
                o0 = (o0 > 0.f) ? o0 : NEG_SLOPE * o0;
                o1 = (o1 > 0.f) ? o1 : NEG_SLOPE * o1;
                o2 = (o2 > 0.f) ? o2 : NEG_SLOPE * o2;
                o3 = (o3 > 0.f) ? o3 : NEG_SLOPE * o3;
                *(float4*)&obase[(size_t)row*CC + col] =
                    make_float4(o0*mk, o1*mk, o2*mk, o3*mk);
            }
        }
    }
}

// ---------------- launch ----------------
extern "C" void kernel_launch(void* const* d_in, const int* in_sizes, int n_in,
                              void* d_out, int out_size) {
    const float* in     = (const float*)d_in[0];
    const float* mask   = (const float*)d_in[1];
    // d_in[2] = nobj (unused: reference hard-codes average_nobj = 49)
    const float* c00    = (const float*)d_in[3];
    const float* c01    = (const float*)d_in[4];
    const float* c10    = (const float*)d_in[5];
    const float* c11    = (const float*)d_in[6];
    const float* bias   = (const float*)d_in[7];
    const float* dbias  = (const float*)d_in[8];
    float* out = (float*)d_out;

    stats_kernel<<<BB*NN, 256>>>(in, c00, c01, c10, c11);
    tw_kernel<<<BB, 256>>>(c00, c01, c10, c11);
    cgemm_kernel<<<dim3(64, 3), 256>>>(bias, dbias);
    main_mma_kernel<<<BB*NN*2, 256, DSM_BYTES>>>(in, mask, out);
}